// round 8
// baseline (speedup 1.0000x reference)
#include <cuda_runtime.h>
#include <cuda_bf16.h>
#include <cstdint>
#include <math.h>

#define NN 8192
#define DD 128
#define NE (NN*3)

// ---------------- device scratch (no allocations allowed) ----------------
__device__ float g_sq[NN];
__device__ __nv_bfloat16 g_xbf[(size_t)NN*DD];
__device__ unsigned long long g_cand[2ull*NN*16];   // [split][row][16] approx top keys
__device__ int g_nbr[NE];
__device__ float g_xp[(size_t)NN*256];    // x @ W, [N][H=2][128]
__device__ float g_as[NN*2];
__device__ float g_ad[NN*2];
__device__ float g_denom[NN*2];
__device__ float g_w[NE*2];
__device__ float g_acc[(size_t)NN*256];   // aggregated messages [N][H][128]

__device__ __forceinline__ unsigned encf(float f){
  unsigned u = __float_as_uint(f);
  return (u & 0x80000000u) ? ~u : (u | 0x80000000u);
}
__device__ __forceinline__ float decf(unsigned u){
  return (u & 0x80000000u) ? __uint_as_float(u ^ 0x80000000u) : __uint_as_float(~u);
}
__device__ __forceinline__ void ins3(unsigned long long k,
                                     unsigned long long &b0,
                                     unsigned long long &b1,
                                     unsigned long long &b2){
  if (k < b2){
    if (k < b1){
      b2 = b1;
      if (k < b0){ b1 = b0; b0 = k; } else { b1 = k; }
    } else { b2 = k; }
  }
}
// caller pre-guards with key < b[3]
__device__ __forceinline__ void ins4(unsigned long long k, unsigned long long* b){
  b[3] = k;
  #pragma unroll
  for (int s = 3; s > 0; s--){
    if (b[s] < b[s-1]){ unsigned long long t = b[s]; b[s] = b[s-1]; b[s-1] = t; }
  }
}

__device__ __forceinline__ uint32_t smem_u32(const void* p){
  uint32_t a;
  asm("{ .reg .u64 t; cvta.to.shared.u64 t, %1; cvt.u32.u64 %0, t; }" : "=r"(a) : "l"(p));
  return a;
}
__device__ __forceinline__ void ldsm4(uint32_t &r0, uint32_t &r1, uint32_t &r2, uint32_t &r3, uint32_t a){
  asm volatile("ldmatrix.sync.aligned.m8n8.x4.shared.b16 {%0,%1,%2,%3}, [%4];"
    : "=r"(r0), "=r"(r1), "=r"(r2), "=r"(r3) : "r"(a));
}
__device__ __forceinline__ void mma16816(float* d, const uint32_t* a, uint32_t b0, uint32_t b1){
  asm volatile("mma.sync.aligned.m16n8k16.row.col.f32.bf16.bf16.f32 "
    "{%0,%1,%2,%3}, {%4,%5,%6,%7}, {%8,%9}, {%0,%1,%2,%3};"
    : "+f"(d[0]), "+f"(d[1]), "+f"(d[2]), "+f"(d[3])
    : "r"(a[0]), "r"(a[1]), "r"(a[2]), "r"(a[3]), "r"(b0), "r"(b1));
}

// ---------------- k1: fused row squared norm + bf16 convert (warp per row) --------
__global__ void k_prep(const float4* __restrict__ X4){
  int g = blockIdx.x*blockDim.x + threadIdx.x;
  int row = g >> 5, lane = g & 31;
  if (row >= NN) return;
  float4 v = X4[row*32 + lane];
  __nv_bfloat162 p0, p1;
  p0.x = __float2bfloat16(v.x); p0.y = __float2bfloat16(v.y);
  p1.x = __float2bfloat16(v.z); p1.y = __float2bfloat16(v.w);
  ((__nv_bfloat162*)g_xbf)[(size_t)row*64 + lane*2]     = p0;
  ((__nv_bfloat162*)g_xbf)[(size_t)row*64 + lane*2 + 1] = p1;
  float s = v.x*v.x + v.y*v.y + v.z*v.z + v.w*v.w;
  #pragma unroll
  for (int o = 16; o; o >>= 1) s += __shfl_xor_sync(0xffffffffu, s, o);
  if (lane == 0) g_sq[row] = s;
}

// ---------------- k2: bf16 mma.sync filter: approx d2 top-4/(row,quarter,split) ----
// grid 128 = 64 i-tiles x 2 j-splits, 256 thr (8 warps, 16 rows/warp).
// smem rows pitch 272B (17 x 16B chunks) -> ldmatrix conflict-free, no swizzle.
static constexpr int PITCH  = 272;
static constexpr int SM_A   = 0;                    // 128*272 = 34816
static constexpr int SM_B0  = 34816;
static constexpr int SM_B1  = 69632;
static constexpr int SM_SQ0 = 104448;               // 512
static constexpr int SM_SQ1 = 104960;               // 512
static constexpr int SM_TOT = 105472;

__global__ __launch_bounds__(256, 1) void k_filter(){
  extern __shared__ char smem[];
  uint32_t sbase = smem_u32(smem);
  int tid = threadIdx.x;
  int w = tid >> 5, lane = tid & 31;
  int ib = blockIdx.x >> 1, split = blockIdx.x & 1;
  int i0 = ib*128;

  // load A tile
  #pragma unroll
  for (int l = 0; l < 8; l++){
    int idx = tid + l*256;
    int r = idx >> 4, c = idx & 15;
    uint4 v = ((const uint4*)(g_xbf + (size_t)(i0 + r)*128))[c];
    *(uint4*)(smem + SM_A + r*PITCH + c*16) = v;
  }
  // load B tile 0 + sq0
  {
    int j0 = split*4096;
    #pragma unroll
    for (int l = 0; l < 8; l++){
      int idx = tid + l*256;
      int r = idx >> 4, c = idx & 15;
      uint4 v = ((const uint4*)(g_xbf + (size_t)(j0 + r)*128))[c];
      *(uint4*)(smem + SM_B0 + r*PITCH + c*16) = v;
    }
    if (tid < 128) ((float*)(smem + SM_SQ0))[tid] = g_sq[j0 + tid];
  }
  __syncthreads();

  uint32_t aAddr = sbase + SM_A
                 + (uint32_t)(16*w + (lane & 7) + 8*((lane >> 3) & 1))*PITCH
                 + (uint32_t)(((lane >> 4) & 1) << 4);
  uint32_t bRowOff = (uint32_t)((lane & 7) + 8*((lane >> 4) & 1))*PITCH
                   + (uint32_t)(((lane >> 3) & 1) << 4);

  unsigned long long bu[4], bl[4];
  #pragma unroll
  for (int s = 0; s < 4; s++){ bu[s] = ~0ull; bl[s] = ~0ull; }
  float thrU = 1e30f, thrL = 1e30f;   // sentinel-safe via fminf(NaN, 1e30)=1e30

  int q = lane & 3;
  int rsub = lane >> 2;

  for (int t = 0; t < 32; t++){
    int j0 = split*4096 + t*128;
    uint32_t bBase = sbase + ((t & 1) ? SM_B1 : SM_B0);
    const float* sq = (const float*)(smem + ((t & 1) ? SM_SQ1 : SM_SQ0));

    uint4 pf[8]; float sqv = 0.f;
    if (t < 31){
      int j0n = j0 + 128;
      #pragma unroll
      for (int l = 0; l < 8; l++){
        int idx = tid + l*256;
        int r = idx >> 4, c = idx & 15;
        pf[l] = ((const uint4*)(g_xbf + (size_t)(j0n + r)*128))[c];
      }
      if (tid < 128) sqv = g_sq[j0n + tid];
    }

    float acc[16][4];
    #pragma unroll
    for (int a = 0; a < 16; a++)
      #pragma unroll
      for (int b = 0; b < 4; b++) acc[a][b] = 0.f;

    #pragma unroll
    for (int ks = 0; ks < 8; ks++){
      uint32_t A[4];
      ldsm4(A[0], A[1], A[2], A[3], aAddr + ks*32);
      #pragma unroll
      for (int p = 0; p < 8; p++){
        uint32_t b0, b1, b2, b3;
        ldsm4(b0, b1, b2, b3, bBase + bRowOff + (uint32_t)(p*16)*PITCH + ks*32);
        mma16816(acc[2*p],   A, b0, b1);
        mma16816(acc[2*p+1], A, b2, b3);
      }
    }

    // epilogue: d2 = sq_j - 2*dot; float-threshold fast path (NaN-safe update)
    #pragma unroll
    for (int tt = 0; tt < 16; tt++){
      int c0 = tt*8 + 2*q;
      float sq0 = sq[c0], sq1 = sq[c0 + 1];
      float du0 = fmaf(-2.0f, acc[tt][0], sq0);
      float du1 = fmaf(-2.0f, acc[tt][1], sq1);
      float dl0 = fmaf(-2.0f, acc[tt][2], sq0);
      float dl1 = fmaf(-2.0f, acc[tt][3], sq1);
      if (du0 < thrU){
        ins4(((unsigned long long)encf(du0) << 32) | (unsigned)(j0 + c0), bu);
        thrU = fminf(decf((unsigned)(bu[3] >> 32)), 1e30f);
      }
      if (du1 < thrU){
        ins4(((unsigned long long)encf(du1) << 32) | (unsigned)(j0 + c0 + 1), bu);
        thrU = fminf(decf((unsigned)(bu[3] >> 32)), 1e30f);
      }
      if (dl0 < thrL){
        ins4(((unsigned long long)encf(dl0) << 32) | (unsigned)(j0 + c0), bl);
        thrL = fminf(decf((unsigned)(bl[3] >> 32)), 1e30f);
      }
      if (dl1 < thrL){
        ins4(((unsigned long long)encf(dl1) << 32) | (unsigned)(j0 + c0 + 1), bl);
        thrL = fminf(decf((unsigned)(bl[3] >> 32)), 1e30f);
      }
    }

    if (t < 31){
      char* nb = smem + (((t + 1) & 1) ? SM_B1 : SM_B0);
      #pragma unroll
      for (int l = 0; l < 8; l++){
        int idx = tid + l*256;
        int r = idx >> 4, c = idx & 15;
        *(uint4*)(nb + r*PITCH + c*16) = pf[l];
      }
      if (tid < 128) ((float*)(smem + (((t + 1) & 1) ? SM_SQ1 : SM_SQ0)))[tid] = sqv;
    }
    __syncthreads();
  }

  int rowU = i0 + 16*w + rsub;
  int rowL = rowU + 8;
  size_t baseU = ((size_t)split*NN + rowU)*16 + q*4;
  size_t baseL = ((size_t)split*NN + rowL)*16 + q*4;
  #pragma unroll
  for (int s = 0; s < 4; s++){
    g_cand[baseU + s] = bu[s];
    g_cand[baseL + s] = bl[s];
  }
}

// ---------------- k3: exact fp32 rescore of 32 candidates -> top-3 ----------------
// warp per row; 4 independent accumulators + full unroll -> high MLP
__global__ __launch_bounds__(256) void k_rescore(const float* __restrict__ X){
  int g = blockIdx.x*blockDim.x + threadIdx.x;
  int row = g >> 5, lane = g & 31;
  if (row >= NN) return;
  int split = lane >> 4;
  unsigned long long ck = g_cand[((size_t)split*NN + row)*16 + (lane & 15)];
  int j = (int)(ck & 0xffffffffull) & (NN - 1);
  const float4* __restrict__ xi = (const float4*)(X + (size_t)row*128);
  const float4* __restrict__ xj = (const float4*)(X + (size_t)j*128);
  float d0 = 0.f, d1 = 0.f, d2acc = 0.f, d3 = 0.f;
  #pragma unroll
  for (int k = 0; k < 32; k += 4){
    float4 a0 = xi[k],   b0 = xj[k];
    float4 a1 = xi[k+1], b1 = xj[k+1];
    float4 a2 = xi[k+2], b2 = xj[k+2];
    float4 a3 = xi[k+3], b3 = xj[k+3];
    d0 = fmaf(a0.x, b0.x, d0); d0 = fmaf(a0.y, b0.y, d0);
    d0 = fmaf(a0.z, b0.z, d0); d0 = fmaf(a0.w, b0.w, d0);
    d1 = fmaf(a1.x, b1.x, d1); d1 = fmaf(a1.y, b1.y, d1);
    d1 = fmaf(a1.z, b1.z, d1); d1 = fmaf(a1.w, b1.w, d1);
    d2acc = fmaf(a2.x, b2.x, d2acc); d2acc = fmaf(a2.y, b2.y, d2acc);
    d2acc = fmaf(a2.z, b2.z, d2acc); d2acc = fmaf(a2.w, b2.w, d2acc);
    d3 = fmaf(a3.x, b3.x, d3); d3 = fmaf(a3.y, b3.y, d3);
    d3 = fmaf(a3.z, b3.z, d3); d3 = fmaf(a3.w, b3.w, d3);
  }
  float dot = (d0 + d1) + (d2acc + d3);
  float d2 = (g_sq[row] + g_sq[j]) - 2.0f*dot;
  unsigned long long b0 = ((unsigned long long)encf(d2) << 32) | (unsigned)j;
  unsigned long long b1 = ~0ull, b2 = ~0ull;
  #pragma unroll
  for (int o = 16; o; o >>= 1){
    unsigned long long c0 = __shfl_xor_sync(0xffffffffu, b0, o);
    unsigned long long c1 = __shfl_xor_sync(0xffffffffu, b1, o);
    unsigned long long c2 = __shfl_xor_sync(0xffffffffu, b2, o);
    ins3(c0, b0, b1, b2);
    ins3(c1, b0, b1, b2);
    ins3(c2, b0, b1, b2);
  }
  if (lane == 0){
    g_nbr[row*3+0] = (int)(b0 & 0xffffffffull);
    g_nbr[row*3+1] = (int)(b1 & 0xffffffffull);
    g_nbr[row*3+2] = (int)(b2 & 0xffffffffull);
  }
}

// ---------------- k4: xp = x @ W (grid 256 = 128 i-tiles(64) x 2 heads) -----------
__global__ __launch_bounds__(256) void k_xp(const float* __restrict__ X,
                                            const float* __restrict__ W){
  __shared__ float sA[32*65];     // 32 k x 64 rows (pitch 65)
  __shared__ float sW[32*129];    // 32 k x 128 cols (pitch 129)
  const float4* X4 = (const float4*)X;
  const float4* W4 = (const float4*)W;
  int tid = threadIdx.x;
  int tx = tid & 15, ty = tid >> 4;
  int ib = blockIdx.x >> 1, h = blockIdx.x & 1;
  int i0 = ib*64;
  float acc[4][8];
  #pragma unroll
  for (int a = 0; a < 4; a++)
    #pragma unroll
    for (int b = 0; b < 8; b++) acc[a][b] = 0.f;

  for (int kc = 0; kc < 4; kc++){
    __syncthreads();
    #pragma unroll
    for (int l = 0; l < 2; l++){
      int idx = tid + l*256;            // 512 float4 chunks of A
      int r = idx >> 3, k4 = idx & 7;
      float4 va = X4[(size_t)(i0 + r)*32 + kc*8 + k4];
      sA[(k4*4+0)*65 + r] = va.x;
      sA[(k4*4+1)*65 + r] = va.y;
      sA[(k4*4+2)*65 + r] = va.z;
      sA[(k4*4+3)*65 + r] = va.w;
    }
    #pragma unroll
    for (int l = 0; l < 4; l++){
      int idx = tid + l*256;            // 1024 float4 chunks of W
      int dd = idx >> 5, c4 = idx & 31;
      float4 vw = W4[(size_t)(kc*32 + dd)*64 + h*32 + c4];
      sW[dd*129 + c4*4 + 0] = vw.x;
      sW[dd*129 + c4*4 + 1] = vw.y;
      sW[dd*129 + c4*4 + 2] = vw.z;
      sW[dd*129 + c4*4 + 3] = vw.w;
    }
    __syncthreads();
    #pragma unroll 4
    for (int k = 0; k < 32; k++){
      float a[4], b[8];
      #pragma unroll
      for (int m = 0; m < 4; m++) a[m] = sA[k*65 + ty + 16*m];
      #pragma unroll
      for (int m = 0; m < 8; m++) b[m] = sW[k*129 + tx + 16*m];
      #pragma unroll
      for (int mi = 0; mi < 4; mi++)
        #pragma unroll
        for (int mj = 0; mj < 8; mj++)
          acc[mi][mj] = fmaf(a[mi], b[mj], acc[mi][mj]);
    }
  }
  #pragma unroll
  for (int mi = 0; mi < 4; mi++)
    #pragma unroll
    for (int mj = 0; mj < 8; mj++)
      g_xp[(size_t)(i0 + ty + 16*mi)*256 + h*128 + tx + 16*mj] = acc[mi][mj];
}

// ---------------- k5: attention coeffs + init denom/acc ----------------
__global__ void k_attn(const float* __restrict__ att_src,
                       const float* __restrict__ att_dst){
  int g = blockIdx.x*blockDim.x + threadIdx.x;
  int n = g >> 5, lane = g & 31;
  if (n >= NN) return;
  const float4* xp4 = (const float4*)g_xp;
  float4 x0 = xp4[(size_t)n*64 + lane];
  float4 x1 = xp4[(size_t)n*64 + 32 + lane];
  const float4* s4 = (const float4*)att_src;
  const float4* d4 = (const float4*)att_dst;
  float4 a0 = s4[lane], a1 = s4[32 + lane];
  float4 c0 = d4[lane], c1 = d4[32 + lane];
  float vs0 = x0.x*a0.x + x0.y*a0.y + x0.z*a0.z + x0.w*a0.w;
  float vs1 = x1.x*a1.x + x1.y*a1.y + x1.z*a1.z + x1.w*a1.w;
  float vd0 = x0.x*c0.x + x0.y*c0.y + x0.z*c0.z + x0.w*c0.w;
  float vd1 = x1.x*c1.x + x1.y*c1.y + x1.z*c1.z + x1.w*c1.w;
  #pragma unroll
  for (int o = 16; o; o >>= 1){
    vs0 += __shfl_xor_sync(0xffffffffu, vs0, o);
    vs1 += __shfl_xor_sync(0xffffffffu, vs1, o);
    vd0 += __shfl_xor_sync(0xffffffffu, vd0, o);
    vd1 += __shfl_xor_sync(0xffffffffu, vd1, o);
  }
  if (lane == 0){
    g_as[n*2+0] = vs0; g_as[n*2+1] = vs1;
    g_ad[n*2+0] = vd0; g_ad[n*2+1] = vd1;
    g_denom[n*2+0] = 0.f; g_denom[n*2+1] = 0.f;
  }
  float4 z = make_float4(0.f, 0.f, 0.f, 0.f);
  ((float4*)g_acc)[(size_t)n*64 + lane] = z;
  ((float4*)g_acc)[(size_t)n*64 + 32 + lane] = z;
}

// ---------------- k6: exp + segment sum (no max-shift: |e| small, fp32-safe) -------
__global__ void k_esum(){
  int idx = blockIdx.x*blockDim.x + threadIdx.x;
  if (idx >= NE*2) return;
  int e = idx >> 1, h = idx & 1;
  int s = e/3;
  int d = g_nbr[e];
  float v = g_as[s*2+h] + g_ad[d*2+h];
  v = v > 0.f ? v : 0.2f*v;
  float w = __expf(v);
  g_w[idx] = w;
  atomicAdd(&g_denom[d*2+h], w);
}

// ---------------- k7: aggregate messages (warp per edge-head) ----------------
__global__ void k_agg(){
  int g = blockIdx.x*blockDim.x + threadIdx.x;
  int eh = g >> 5, lane = g & 31;
  if (eh >= NE*2) return;
  int e = eh >> 1, h = eh & 1;
  int s = e/3;
  int d = g_nbr[e];
  float alpha = g_w[eh] / g_denom[d*2+h];
  const float4* xp4 = (const float4*)g_xp;
  float4 v = xp4[(size_t)s*64 + h*32 + lane];
  float* dst = &g_acc[(size_t)d*256 + h*128 + lane*4];
  atomicAdd(dst+0, alpha*v.x);
  atomicAdd(dst+1, alpha*v.y);
  atomicAdd(dst+2, alpha*v.z);
  atomicAdd(dst+3, alpha*v.w);
}

// ---------------- k8: head-mean + bias + LayerNorm + ReLU + residual ----------------
__global__ void k_final(const float* __restrict__ X,
                        const float* __restrict__ bias,
                        const float* __restrict__ gamma,
                        const float* __restrict__ beta,
                        float* __restrict__ out){
  int g = blockIdx.x*blockDim.x + threadIdx.x;
  int n = g >> 5, lane = g & 31;
  if (n >= NN) return;
  float v[4];
  #pragma unroll
  for (int c = 0; c < 4; c++){
    int dd = lane*4 + c;
    float a0 = g_acc[(size_t)n*256 + dd];
    float a1 = g_acc[(size_t)n*256 + 128 + dd];
    v[c] = 0.5f*(a0 + a1) + bias[dd];
  }
  float s = v[0]+v[1]+v[2]+v[3];
  #pragma unroll
  for (int o = 16; o; o >>= 1) s += __shfl_xor_sync(0xffffffffu, s, o);
  float mu = s * (1.0f/128.0f);
  float q = 0.f;
  #pragma unroll
  for (int c = 0; c < 4; c++){ float t = v[c]-mu; q += t*t; }
  #pragma unroll
  for (int o = 16; o; o >>= 1) q += __shfl_xor_sync(0xffffffffu, q, o);
  float rstd = rsqrtf(q*(1.0f/128.0f) + 1e-5f);
  #pragma unroll
  for (int c = 0; c < 4; c++){
    int dd = lane*4 + c;
    float y = (v[c]-mu)*rstd*gamma[dd] + beta[dd];
    y = y > 0.f ? y : 0.f;
    out[(size_t)n*128 + dd] = X[(size_t)n*128 + dd] + y;
  }
}

// ---------------- launch ----------------
extern "C" void kernel_launch(void* const* d_in, const int* in_sizes, int n_in,
                              void* d_out, int out_size) {
  const float* prototypes = (const float*)d_in[0];
  // d_in[1] = labels (unused in forward)
  const float* W       = (const float*)d_in[2];
  const float* att_src = (const float*)d_in[3];
  const float* att_dst = (const float*)d_in[4];
  const float* bias    = (const float*)d_in[5];
  const float* gamma   = (const float*)d_in[6];
  const float* beta    = (const float*)d_in[7];
  float* out = (float*)d_out;

  cudaFuncSetAttribute(k_filter, cudaFuncAttributeMaxDynamicSharedMemorySize, SM_TOT);

  k_prep<<<NN/8, 256>>>((const float4*)prototypes);
  k_filter<<<128, 256, SM_TOT>>>();
  k_rescore<<<NN/8, 256>>>(prototypes);
  k_xp<<<256, 256>>>(prototypes, W);
  k_attn<<<NN/8, 256>>>(att_src, att_dst);
  k_esum<<<(NE*2+255)/256, 256>>>();
  k_agg<<<(NE*2*32+255)/256, 256>>>();
  k_final<<<NN/8, 256>>>(prototypes, bias, gamma, beta, out);
}

// round 9
// speedup vs baseline: 1.0859x; 1.0859x over previous
#include <cuda_runtime.h>
#include <cuda_bf16.h>
#include <cstdint>
#include <math.h>

#define NN 8192
#define DD 128
#define NE (NN*3)

// ---------------- device scratch (no allocations allowed) ----------------
__device__ float g_sq[NN];
__device__ __nv_bfloat16 g_xbf[(size_t)NN*DD];
__device__ unsigned long long g_cand[2ull*NN*16];   // [split][row][16] approx top keys
__device__ int g_nbr[NE];
__device__ float g_xp[(size_t)NN*256];    // x @ W, [N][H=2][128]
__device__ float g_as[NN*2];
__device__ float g_ad[NN*2];
__device__ float g_denom[NN*2];
__device__ float g_acc[(size_t)NN*256];   // unnormalized messages [N][H][128]

__device__ __forceinline__ unsigned encf(float f){
  unsigned u = __float_as_uint(f);
  return (u & 0x80000000u) ? ~u : (u | 0x80000000u);
}
__device__ __forceinline__ float decf(unsigned u){
  return (u & 0x80000000u) ? __uint_as_float(u ^ 0x80000000u) : __uint_as_float(~u);
}
__device__ __forceinline__ void ins3(unsigned long long k,
                                     unsigned long long &b0,
                                     unsigned long long &b1,
                                     unsigned long long &b2){
  if (k < b2){
    if (k < b1){
      b2 = b1;
      if (k < b0){ b1 = b0; b0 = k; } else { b1 = k; }
    } else { b2 = k; }
  }
}
// caller pre-guards with key < b[3]
__device__ __forceinline__ void ins4(unsigned long long k, unsigned long long* b){
  b[3] = k;
  #pragma unroll
  for (int s = 3; s > 0; s--){
    if (b[s] < b[s-1]){ unsigned long long t = b[s]; b[s] = b[s-1]; b[s-1] = t; }
  }
}

__device__ __forceinline__ uint32_t smem_u32(const void* p){
  uint32_t a;
  asm("{ .reg .u64 t; cvta.to.shared.u64 t, %1; cvt.u32.u64 %0, t; }" : "=r"(a) : "l"(p));
  return a;
}
__device__ __forceinline__ void ldsm4(uint32_t &r0, uint32_t &r1, uint32_t &r2, uint32_t &r3, uint32_t a){
  asm volatile("ldmatrix.sync.aligned.m8n8.x4.shared.b16 {%0,%1,%2,%3}, [%4];"
    : "=r"(r0), "=r"(r1), "=r"(r2), "=r"(r3) : "r"(a));
}
__device__ __forceinline__ void mma16816(float* d, const uint32_t* a, uint32_t b0, uint32_t b1){
  asm volatile("mma.sync.aligned.m16n8k16.row.col.f32.bf16.bf16.f32 "
    "{%0,%1,%2,%3}, {%4,%5,%6,%7}, {%8,%9}, {%0,%1,%2,%3};"
    : "+f"(d[0]), "+f"(d[1]), "+f"(d[2]), "+f"(d[3])
    : "r"(a[0]), "r"(a[1]), "r"(a[2]), "r"(a[3]), "r"(b0), "r"(b1));
}

// ---------------- k1: fused row squared norm + bf16 convert (warp per row) --------
__global__ void k_prep(const float4* __restrict__ X4){
  int g = blockIdx.x*blockDim.x + threadIdx.x;
  int row = g >> 5, lane = g & 31;
  if (row >= NN) return;
  float4 v = X4[row*32 + lane];
  __nv_bfloat162 p0, p1;
  p0.x = __float2bfloat16(v.x); p0.y = __float2bfloat16(v.y);
  p1.x = __float2bfloat16(v.z); p1.y = __float2bfloat16(v.w);
  ((__nv_bfloat162*)g_xbf)[(size_t)row*64 + lane*2]     = p0;
  ((__nv_bfloat162*)g_xbf)[(size_t)row*64 + lane*2 + 1] = p1;
  float s = v.x*v.x + v.y*v.y + v.z*v.z + v.w*v.w;
  #pragma unroll
  for (int o = 16; o; o >>= 1) s += __shfl_xor_sync(0xffffffffu, s, o);
  if (lane == 0) g_sq[row] = s;
}

// ---------------- k2: bf16 mma.sync filter (unchanged from R7 win) ----------------
static constexpr int PITCH  = 272;
static constexpr int SM_A   = 0;
static constexpr int SM_B0  = 34816;
static constexpr int SM_B1  = 69632;
static constexpr int SM_SQ0 = 104448;
static constexpr int SM_SQ1 = 104960;
static constexpr int SM_TOT = 105472;

__global__ __launch_bounds__(256, 1) void k_filter(){
  extern __shared__ char smem[];
  uint32_t sbase = smem_u32(smem);
  int tid = threadIdx.x;
  int w = tid >> 5, lane = tid & 31;
  int ib = blockIdx.x >> 1, split = blockIdx.x & 1;
  int i0 = ib*128;

  #pragma unroll
  for (int l = 0; l < 8; l++){
    int idx = tid + l*256;
    int r = idx >> 4, c = idx & 15;
    uint4 v = ((const uint4*)(g_xbf + (size_t)(i0 + r)*128))[c];
    *(uint4*)(smem + SM_A + r*PITCH + c*16) = v;
  }
  {
    int j0 = split*4096;
    #pragma unroll
    for (int l = 0; l < 8; l++){
      int idx = tid + l*256;
      int r = idx >> 4, c = idx & 15;
      uint4 v = ((const uint4*)(g_xbf + (size_t)(j0 + r)*128))[c];
      *(uint4*)(smem + SM_B0 + r*PITCH + c*16) = v;
    }
    if (tid < 128) ((float*)(smem + SM_SQ0))[tid] = g_sq[j0 + tid];
  }
  __syncthreads();

  uint32_t aAddr = sbase + SM_A
                 + (uint32_t)(16*w + (lane & 7) + 8*((lane >> 3) & 1))*PITCH
                 + (uint32_t)(((lane >> 4) & 1) << 4);
  uint32_t bRowOff = (uint32_t)((lane & 7) + 8*((lane >> 4) & 1))*PITCH
                   + (uint32_t)(((lane >> 3) & 1) << 4);

  unsigned long long bu[4], bl[4];
  #pragma unroll
  for (int s = 0; s < 4; s++){ bu[s] = ~0ull; bl[s] = ~0ull; }
  float thrU = 1e30f, thrL = 1e30f;

  int q = lane & 3;
  int rsub = lane >> 2;

  for (int t = 0; t < 32; t++){
    int j0 = split*4096 + t*128;
    uint32_t bBase = sbase + ((t & 1) ? SM_B1 : SM_B0);
    const float* sq = (const float*)(smem + ((t & 1) ? SM_SQ1 : SM_SQ0));

    uint4 pf[8]; float sqv = 0.f;
    if (t < 31){
      int j0n = j0 + 128;
      #pragma unroll
      for (int l = 0; l < 8; l++){
        int idx = tid + l*256;
        int r = idx >> 4, c = idx & 15;
        pf[l] = ((const uint4*)(g_xbf + (size_t)(j0n + r)*128))[c];
      }
      if (tid < 128) sqv = g_sq[j0n + tid];
    }

    float acc[16][4];
    #pragma unroll
    for (int a = 0; a < 16; a++)
      #pragma unroll
      for (int b = 0; b < 4; b++) acc[a][b] = 0.f;

    #pragma unroll
    for (int ks = 0; ks < 8; ks++){
      uint32_t A[4];
      ldsm4(A[0], A[1], A[2], A[3], aAddr + ks*32);
      #pragma unroll
      for (int p = 0; p < 8; p++){
        uint32_t b0, b1, b2, b3;
        ldsm4(b0, b1, b2, b3, bBase + bRowOff + (uint32_t)(p*16)*PITCH + ks*32);
        mma16816(acc[2*p],   A, b0, b1);
        mma16816(acc[2*p+1], A, b2, b3);
      }
    }

    #pragma unroll
    for (int tt = 0; tt < 16; tt++){
      int c0 = tt*8 + 2*q;
      float sq0 = sq[c0], sq1 = sq[c0 + 1];
      float du0 = fmaf(-2.0f, acc[tt][0], sq0);
      float du1 = fmaf(-2.0f, acc[tt][1], sq1);
      float dl0 = fmaf(-2.0f, acc[tt][2], sq0);
      float dl1 = fmaf(-2.0f, acc[tt][3], sq1);
      if (du0 < thrU){
        ins4(((unsigned long long)encf(du0) << 32) | (unsigned)(j0 + c0), bu);
        thrU = fminf(decf((unsigned)(bu[3] >> 32)), 1e30f);
      }
      if (du1 < thrU){
        ins4(((unsigned long long)encf(du1) << 32) | (unsigned)(j0 + c0 + 1), bu);
        thrU = fminf(decf((unsigned)(bu[3] >> 32)), 1e30f);
      }
      if (dl0 < thrL){
        ins4(((unsigned long long)encf(dl0) << 32) | (unsigned)(j0 + c0), bl);
        thrL = fminf(decf((unsigned)(bl[3] >> 32)), 1e30f);
      }
      if (dl1 < thrL){
        ins4(((unsigned long long)encf(dl1) << 32) | (unsigned)(j0 + c0 + 1), bl);
        thrL = fminf(decf((unsigned)(bl[3] >> 32)), 1e30f);
      }
    }

    if (t < 31){
      char* nb = smem + (((t + 1) & 1) ? SM_B1 : SM_B0);
      #pragma unroll
      for (int l = 0; l < 8; l++){
        int idx = tid + l*256;
        int r = idx >> 4, c = idx & 15;
        *(uint4*)(nb + r*PITCH + c*16) = pf[l];
      }
      if (tid < 128) ((float*)(smem + (((t + 1) & 1) ? SM_SQ1 : SM_SQ0)))[tid] = sqv;
    }
    __syncthreads();
  }

  int rowU = i0 + 16*w + rsub;
  int rowL = rowU + 8;
  size_t baseU = ((size_t)split*NN + rowU)*16 + q*4;
  size_t baseL = ((size_t)split*NN + rowL)*16 + q*4;
  #pragma unroll
  for (int s = 0; s < 4; s++){
    g_cand[baseU + s] = bu[s];
    g_cand[baseL + s] = bl[s];
  }
}

// ---------------- k3: exact fp32 rescore v2 — warp per row, coalesced -------------
// lane l holds xi[l] (float4); per candidate: coalesced xj load + butterfly reduce.
__global__ __launch_bounds__(256) void k_rescore(const float* __restrict__ X){
  int g = blockIdx.x*blockDim.x + threadIdx.x;
  int row = g >> 5, lane = g & 31;
  if (row >= NN) return;
  const float4* __restrict__ X4 = (const float4*)X;
  float4 xi = X4[(size_t)row*32 + lane];
  // lane l -> candidate l: split = l>>4, slot = l&15
  unsigned long long ck = g_cand[((size_t)(lane >> 4)*NN + row)*16 + (lane & 15)];
  int jl = (int)(ck & 0xffffffffull) & (NN - 1);
  float sqi = g_sq[row];
  unsigned long long b0 = ~0ull, b1 = ~0ull, b2 = ~0ull;
  #pragma unroll 4
  for (int c = 0; c < 32; c++){
    int j = __shfl_sync(0xffffffffu, jl, c);
    float4 xj = X4[(size_t)j*32 + lane];
    float p = xi.x*xj.x + xi.y*xj.y + xi.z*xj.z + xi.w*xj.w;
    #pragma unroll
    for (int o = 16; o; o >>= 1) p += __shfl_xor_sync(0xffffffffu, p, o);
    float d2 = (sqi + g_sq[j]) - 2.0f*p;
    unsigned long long key = ((unsigned long long)encf(d2) << 32) | (unsigned)j;
    ins3(key, b0, b1, b2);
  }
  if (lane == 0){
    g_nbr[row*3+0] = (int)(b0 & 0xffffffffull);
    g_nbr[row*3+1] = (int)(b1 & 0xffffffffull);
    g_nbr[row*3+2] = (int)(b2 & 0xffffffffull);
  }
}

// ---------------- k4: xp = x @ W (grid 256 = 128 i-tiles(64) x 2 heads) -----------
__global__ __launch_bounds__(256) void k_xp(const float* __restrict__ X,
                                            const float* __restrict__ W){
  __shared__ float sA[32*65];
  __shared__ float sW[32*129];
  const float4* X4 = (const float4*)X;
  const float4* W4 = (const float4*)W;
  int tid = threadIdx.x;
  int tx = tid & 15, ty = tid >> 4;
  int ib = blockIdx.x >> 1, h = blockIdx.x & 1;
  int i0 = ib*64;
  float acc[4][8];
  #pragma unroll
  for (int a = 0; a < 4; a++)
    #pragma unroll
    for (int b = 0; b < 8; b++) acc[a][b] = 0.f;

  for (int kc = 0; kc < 4; kc++){
    __syncthreads();
    #pragma unroll
    for (int l = 0; l < 2; l++){
      int idx = tid + l*256;
      int r = idx >> 3, k4 = idx & 7;
      float4 va = X4[(size_t)(i0 + r)*32 + kc*8 + k4];
      sA[(k4*4+0)*65 + r] = va.x;
      sA[(k4*4+1)*65 + r] = va.y;
      sA[(k4*4+2)*65 + r] = va.z;
      sA[(k4*4+3)*65 + r] = va.w;
    }
    #pragma unroll
    for (int l = 0; l < 4; l++){
      int idx = tid + l*256;
      int dd = idx >> 5, c4 = idx & 31;
      float4 vw = W4[(size_t)(kc*32 + dd)*64 + h*32 + c4];
      sW[dd*129 + c4*4 + 0] = vw.x;
      sW[dd*129 + c4*4 + 1] = vw.y;
      sW[dd*129 + c4*4 + 2] = vw.z;
      sW[dd*129 + c4*4 + 3] = vw.w;
    }
    __syncthreads();
    #pragma unroll 4
    for (int k = 0; k < 32; k++){
      float a[4], b[8];
      #pragma unroll
      for (int m = 0; m < 4; m++) a[m] = sA[k*65 + ty + 16*m];
      #pragma unroll
      for (int m = 0; m < 8; m++) b[m] = sW[k*129 + tx + 16*m];
      #pragma unroll
      for (int mi = 0; mi < 4; mi++)
        #pragma unroll
        for (int mj = 0; mj < 8; mj++)
          acc[mi][mj] = fmaf(a[mi], b[mj], acc[mi][mj]);
    }
  }
  #pragma unroll
  for (int mi = 0; mi < 4; mi++)
    #pragma unroll
    for (int mj = 0; mj < 8; mj++)
      g_xp[(size_t)(i0 + ty + 16*mi)*256 + h*128 + tx + 16*mj] = acc[mi][mj];
}

// ---------------- k5: attention coeffs + init denom/acc ----------------
__global__ void k_attn(const float* __restrict__ att_src,
                       const float* __restrict__ att_dst){
  int g = blockIdx.x*blockDim.x + threadIdx.x;
  int n = g >> 5, lane = g & 31;
  if (n >= NN) return;
  const float4* xp4 = (const float4*)g_xp;
  float4 x0 = xp4[(size_t)n*64 + lane];
  float4 x1 = xp4[(size_t)n*64 + 32 + lane];
  const float4* s4 = (const float4*)att_src;
  const float4* d4 = (const float4*)att_dst;
  float4 a0 = s4[lane], a1 = s4[32 + lane];
  float4 c0 = d4[lane], c1 = d4[32 + lane];
  float vs0 = x0.x*a0.x + x0.y*a0.y + x0.z*a0.z + x0.w*a0.w;
  float vs1 = x1.x*a1.x + x1.y*a1.y + x1.z*a1.z + x1.w*a1.w;
  float vd0 = x0.x*c0.x + x0.y*c0.y + x0.z*c0.z + x0.w*c0.w;
  float vd1 = x1.x*c1.x + x1.y*c1.y + x1.z*c1.z + x1.w*c1.w;
  #pragma unroll
  for (int o = 16; o; o >>= 1){
    vs0 += __shfl_xor_sync(0xffffffffu, vs0, o);
    vs1 += __shfl_xor_sync(0xffffffffu, vs1, o);
    vd0 += __shfl_xor_sync(0xffffffffu, vd0, o);
    vd1 += __shfl_xor_sync(0xffffffffu, vd1, o);
  }
  if (lane == 0){
    g_as[n*2+0] = vs0; g_as[n*2+1] = vs1;
    g_ad[n*2+0] = vd0; g_ad[n*2+1] = vd1;
    g_denom[n*2+0] = 0.f; g_denom[n*2+1] = 0.f;
  }
  float4 z = make_float4(0.f, 0.f, 0.f, 0.f);
  ((float4*)g_acc)[(size_t)n*64 + lane] = z;
  ((float4*)g_acc)[(size_t)n*64 + 32 + lane] = z;
}

// ---------------- k6: fused edge softmax-weight + aggregate (warp per edge-head) --
// Sum alpha*x == (Sum w*x)/denom  -> accumulate w*x and denom; k_final divides.
__global__ void k_edge(){
  int g = blockIdx.x*blockDim.x + threadIdx.x;
  int eh = g >> 5, lane = g & 31;
  if (eh >= NE*2) return;
  int e = eh >> 1, h = eh & 1;
  int s = e/3;
  int d = g_nbr[e];
  float v = g_as[s*2+h] + g_ad[d*2+h];
  v = v > 0.f ? v : 0.2f*v;
  float w = __expf(v);
  if (lane == 0) atomicAdd(&g_denom[d*2+h], w);
  const float4* xp4 = (const float4*)g_xp;
  float4 xv = xp4[(size_t)s*64 + h*32 + lane];
  float* dst = &g_acc[(size_t)d*256 + h*128 + lane*4];
  atomicAdd(dst+0, w*xv.x);
  atomicAdd(dst+1, w*xv.y);
  atomicAdd(dst+2, w*xv.z);
  atomicAdd(dst+3, w*xv.w);
}

// ---------------- k7: normalize + head-mean + bias + LayerNorm + ReLU + residual ----
__global__ void k_final(const float* __restrict__ X,
                        const float* __restrict__ bias,
                        const float* __restrict__ gamma,
                        const float* __restrict__ beta,
                        float* __restrict__ out){
  int g = blockIdx.x*blockDim.x + threadIdx.x;
  int n = g >> 5, lane = g & 31;
  if (n >= NN) return;
  float inv0 = 1.0f / g_denom[n*2+0];
  float inv1 = 1.0f / g_denom[n*2+1];
  float v[4];
  #pragma unroll
  for (int c = 0; c < 4; c++){
    int dd = lane*4 + c;
    float a0 = g_acc[(size_t)n*256 + dd] * inv0;
    float a1 = g_acc[(size_t)n*256 + 128 + dd] * inv1;
    v[c] = 0.5f*(a0 + a1) + bias[dd];
  }
  float s = v[0]+v[1]+v[2]+v[3];
  #pragma unroll
  for (int o = 16; o; o >>= 1) s += __shfl_xor_sync(0xffffffffu, s, o);
  float mu = s * (1.0f/128.0f);
  float q = 0.f;
  #pragma unroll
  for (int c = 0; c < 4; c++){ float t = v[c]-mu; q += t*t; }
  #pragma unroll
  for (int o = 16; o; o >>= 1) q += __shfl_xor_sync(0xffffffffu, q, o);
  float rstd = rsqrtf(q*(1.0f/128.0f) + 1e-5f);
  #pragma unroll
  for (int c = 0; c < 4; c++){
    int dd = lane*4 + c;
    float y = (v[c]-mu)*rstd*gamma[dd] + beta[dd];
    y = y > 0.f ? y : 0.f;
    out[(size_t)n*128 + dd] = X[(size_t)n*128 + dd] + y;
  }
}

// ---------------- launch ----------------
extern "C" void kernel_launch(void* const* d_in, const int* in_sizes, int n_in,
                              void* d_out, int out_size) {
  const float* prototypes = (const float*)d_in[0];
  // d_in[1] = labels (unused in forward)
  const float* W       = (const float*)d_in[2];
  const float* att_src = (const float*)d_in[3];
  const float* att_dst = (const float*)d_in[4];
  const float* bias    = (const float*)d_in[5];
  const float* gamma   = (const float*)d_in[6];
  const float* beta    = (const float*)d_in[7];
  float* out = (float*)d_out;

  cudaFuncSetAttribute(k_filter, cudaFuncAttributeMaxDynamicSharedMemorySize, SM_TOT);

  k_prep<<<NN/8, 256>>>((const float4*)prototypes);
  k_filter<<<128, 256, SM_TOT>>>();
  k_rescore<<<NN/8, 256>>>(prototypes);
  k_xp<<<256, 256>>>(prototypes, W);
  k_attn<<<NN/8, 256>>>(att_src, att_dst);
  k_edge<<<(NE*2*32+255)/256, 256>>>();
  k_final<<<NN/8, 256>>>(prototypes, bias, gamma, beta, out);
}

// round 10
// speedup vs baseline: 1.1056x; 1.0182x over previous
#include <cuda_runtime.h>
#include <cuda_bf16.h>
#include <cstdint>
#include <math.h>

#define NN 8192
#define DD 128
#define NE (NN*3)

// ---------------- device scratch (no allocations allowed) ----------------
__device__ float g_sq[NN];
__device__ __nv_bfloat16 g_xbf[(size_t)NN*DD];
__device__ unsigned long long g_cand[2ull*NN*16];   // [split][row][16] approx top keys
__device__ int g_nbr[NE];
__device__ float g_xp[(size_t)NN*256];    // x @ W, [N][H=2][128]
__device__ float g_as[NN*2];
__device__ float g_ad[NN*2];
__device__ float g_denom[NN*2];
__device__ float g_acc[(size_t)NN*256];   // unnormalized messages [N][H][128]

__device__ __forceinline__ unsigned encf(float f){
  unsigned u = __float_as_uint(f);
  return (u & 0x80000000u) ? ~u : (u | 0x80000000u);
}
__device__ __forceinline__ float decf(unsigned u){
  return (u & 0x80000000u) ? __uint_as_float(u ^ 0x80000000u) : __uint_as_float(~u);
}
__device__ __forceinline__ void ins3(unsigned long long k,
                                     unsigned long long &b0,
                                     unsigned long long &b1,
                                     unsigned long long &b2){
  if (k < b2){
    if (k < b1){
      b2 = b1;
      if (k < b0){ b1 = b0; b0 = k; } else { b1 = k; }
    } else { b2 = k; }
  }
}
// caller pre-guards with key < b[3]
__device__ __forceinline__ void ins4(unsigned long long k, unsigned long long* b){
  b[3] = k;
  #pragma unroll
  for (int s = 3; s > 0; s--){
    if (b[s] < b[s-1]){ unsigned long long t = b[s]; b[s] = b[s-1]; b[s-1] = t; }
  }
}

__device__ __forceinline__ uint32_t smem_u32(const void* p){
  uint32_t a;
  asm("{ .reg .u64 t; cvta.to.shared.u64 t, %1; cvt.u32.u64 %0, t; }" : "=r"(a) : "l"(p));
  return a;
}
__device__ __forceinline__ void ldsm4(uint32_t &r0, uint32_t &r1, uint32_t &r2, uint32_t &r3, uint32_t a){
  asm volatile("ldmatrix.sync.aligned.m8n8.x4.shared.b16 {%0,%1,%2,%3}, [%4];"
    : "=r"(r0), "=r"(r1), "=r"(r2), "=r"(r3) : "r"(a));
}
__device__ __forceinline__ void mma16816(float* d, const uint32_t* a, uint32_t b0, uint32_t b1){
  asm volatile("mma.sync.aligned.m16n8k16.row.col.f32.bf16.bf16.f32 "
    "{%0,%1,%2,%3}, {%4,%5,%6,%7}, {%8,%9}, {%0,%1,%2,%3};"
    : "+f"(d[0]), "+f"(d[1]), "+f"(d[2]), "+f"(d[3])
    : "r"(a[0]), "r"(a[1]), "r"(a[2]), "r"(a[3]), "r"(b0), "r"(b1));
}

// ---------------- k_prep: fused row squared norm + bf16 convert (warp per row) ----
__global__ void k_prep(const float4* __restrict__ X4){
  int g = blockIdx.x*blockDim.x + threadIdx.x;
  int row = g >> 5, lane = g & 31;
  if (row >= NN) return;
  float4 v = X4[row*32 + lane];
  __nv_bfloat162 p0, p1;
  p0.x = __float2bfloat16(v.x); p0.y = __float2bfloat16(v.y);
  p1.x = __float2bfloat16(v.z); p1.y = __float2bfloat16(v.w);
  ((__nv_bfloat162*)g_xbf)[(size_t)row*64 + lane*2]     = p0;
  ((__nv_bfloat162*)g_xbf)[(size_t)row*64 + lane*2 + 1] = p1;
  float s = v.x*v.x + v.y*v.y + v.z*v.z + v.w*v.w;
  #pragma unroll
  for (int o = 16; o; o >>= 1) s += __shfl_xor_sync(0xffffffffu, s, o);
  if (lane == 0) g_sq[row] = s;
}

// ---------------- k_xp v2: full-K smem, float4 LDS (grid 256 = 128 ib x 2 heads) ---
// thread (tx=tid&15, ty=tid>>4): rows 4ty..4ty+3, cols {4tx..+3, 64+4tx..+3}
static constexpr int XP_SMEM = (128*64 + 128*128) * 4;   // sA 32KB + sW 64KB
__global__ __launch_bounds__(256) void k_xp(const float* __restrict__ X,
                                            const float* __restrict__ W){
  extern __shared__ float xsm[];
  float* sA = xsm;            // [k][row64]
  float* sW = xsm + 128*64;   // [k][col128]
  const float4* X4 = (const float4*)X;
  const float4* W4 = (const float4*)W;
  int tid = threadIdx.x;
  int tx = tid & 15, ty = tid >> 4;
  int ib = blockIdx.x >> 1, h = blockIdx.x & 1;
  int i0 = ib*64;

  // load A: 64 rows x 32 k-chunks = 2048 float4
  #pragma unroll
  for (int l = 0; l < 8; l++){
    int idx = tid + l*256;
    int r = idx & 63, kc = idx >> 6;
    float4 v = X4[(size_t)(i0 + r)*32 + kc];
    sA[(kc*4+0)*64 + r] = v.x;
    sA[(kc*4+1)*64 + r] = v.y;
    sA[(kc*4+2)*64 + r] = v.z;
    sA[(kc*4+3)*64 + r] = v.w;
  }
  // load W head h: 128 k x 32 chunks = 4096 float4
  #pragma unroll
  for (int l = 0; l < 16; l++){
    int idx = tid + l*256;
    int k = idx >> 5, c4 = idx & 31;
    ((float4*)sW)[k*32 + c4] = W4[(size_t)k*64 + h*32 + c4];
  }
  __syncthreads();

  float acc[4][8];
  #pragma unroll
  for (int a = 0; a < 4; a++)
    #pragma unroll
    for (int b = 0; b < 8; b++) acc[a][b] = 0.f;

  #pragma unroll 4
  for (int k = 0; k < 128; k++){
    float4 a4 = *(const float4*)(sA + k*64 + 4*ty);
    float4 b0 = *(const float4*)(sW + k*128 + 4*tx);
    float4 b1 = *(const float4*)(sW + k*128 + 64 + 4*tx);
    float a[4] = {a4.x, a4.y, a4.z, a4.w};
    float b[8] = {b0.x, b0.y, b0.z, b0.w, b1.x, b1.y, b1.z, b1.w};
    #pragma unroll
    for (int mi = 0; mi < 4; mi++)
      #pragma unroll
      for (int mj = 0; mj < 8; mj++)
        acc[mi][mj] = fmaf(a[mi], b[mj], acc[mi][mj]);
  }

  #pragma unroll
  for (int mi = 0; mi < 4; mi++){
    size_t base = (size_t)(i0 + 4*ty + mi)*256 + h*128;
    *(float4*)(g_xp + base + 4*tx)      = make_float4(acc[mi][0], acc[mi][1], acc[mi][2], acc[mi][3]);
    *(float4*)(g_xp + base + 64 + 4*tx) = make_float4(acc[mi][4], acc[mi][5], acc[mi][6], acc[mi][7]);
  }
}

// ---------------- k_attn: attention coeffs + init denom/acc ----------------
__global__ void k_attn(const float* __restrict__ att_src,
                       const float* __restrict__ att_dst){
  int g = blockIdx.x*blockDim.x + threadIdx.x;
  int n = g >> 5, lane = g & 31;
  if (n >= NN) return;
  const float4* xp4 = (const float4*)g_xp;
  float4 x0 = xp4[(size_t)n*64 + lane];
  float4 x1 = xp4[(size_t)n*64 + 32 + lane];
  const float4* s4 = (const float4*)att_src;
  const float4* d4 = (const float4*)att_dst;
  float4 a0 = s4[lane], a1 = s4[32 + lane];
  float4 c0 = d4[lane], c1 = d4[32 + lane];
  float vs0 = x0.x*a0.x + x0.y*a0.y + x0.z*a0.z + x0.w*a0.w;
  float vs1 = x1.x*a1.x + x1.y*a1.y + x1.z*a1.z + x1.w*a1.w;
  float vd0 = x0.x*c0.x + x0.y*c0.y + x0.z*c0.z + x0.w*c0.w;
  float vd1 = x1.x*c1.x + x1.y*c1.y + x1.z*c1.z + x1.w*c1.w;
  #pragma unroll
  for (int o = 16; o; o >>= 1){
    vs0 += __shfl_xor_sync(0xffffffffu, vs0, o);
    vs1 += __shfl_xor_sync(0xffffffffu, vs1, o);
    vd0 += __shfl_xor_sync(0xffffffffu, vd0, o);
    vd1 += __shfl_xor_sync(0xffffffffu, vd1, o);
  }
  if (lane == 0){
    g_as[n*2+0] = vs0; g_as[n*2+1] = vs1;
    g_ad[n*2+0] = vd0; g_ad[n*2+1] = vd1;
    g_denom[n*2+0] = 0.f; g_denom[n*2+1] = 0.f;
  }
  float4 z = make_float4(0.f, 0.f, 0.f, 0.f);
  ((float4*)g_acc)[(size_t)n*64 + lane] = z;
  ((float4*)g_acc)[(size_t)n*64 + 32 + lane] = z;
}

// ---------------- k_filter: bf16 mma.sync filter (unchanged; now at profile slot) --
static constexpr int PITCH  = 272;
static constexpr int SM_A   = 0;
static constexpr int SM_B0  = 34816;
static constexpr int SM_B1  = 69632;
static constexpr int SM_SQ0 = 104448;
static constexpr int SM_SQ1 = 104960;
static constexpr int SM_TOT = 105472;

__global__ __launch_bounds__(256, 1) void k_filter(){
  extern __shared__ char smem[];
  uint32_t sbase = smem_u32(smem);
  int tid = threadIdx.x;
  int w = tid >> 5, lane = tid & 31;
  int ib = blockIdx.x >> 1, split = blockIdx.x & 1;
  int i0 = ib*128;

  #pragma unroll
  for (int l = 0; l < 8; l++){
    int idx = tid + l*256;
    int r = idx >> 4, c = idx & 15;
    uint4 v = ((const uint4*)(g_xbf + (size_t)(i0 + r)*128))[c];
    *(uint4*)(smem + SM_A + r*PITCH + c*16) = v;
  }
  {
    int j0 = split*4096;
    #pragma unroll
    for (int l = 0; l < 8; l++){
      int idx = tid + l*256;
      int r = idx >> 4, c = idx & 15;
      uint4 v = ((const uint4*)(g_xbf + (size_t)(j0 + r)*128))[c];
      *(uint4*)(smem + SM_B0 + r*PITCH + c*16) = v;
    }
    if (tid < 128) ((float*)(smem + SM_SQ0))[tid] = g_sq[j0 + tid];
  }
  __syncthreads();

  uint32_t aAddr = sbase + SM_A
                 + (uint32_t)(16*w + (lane & 7) + 8*((lane >> 3) & 1))*PITCH
                 + (uint32_t)(((lane >> 4) & 1) << 4);
  uint32_t bRowOff = (uint32_t)((lane & 7) + 8*((lane >> 4) & 1))*PITCH
                   + (uint32_t)(((lane >> 3) & 1) << 4);

  unsigned long long bu[4], bl[4];
  #pragma unroll
  for (int s = 0; s < 4; s++){ bu[s] = ~0ull; bl[s] = ~0ull; }
  float thrU = 1e30f, thrL = 1e30f;

  int q = lane & 3;
  int rsub = lane >> 2;

  for (int t = 0; t < 32; t++){
    int j0 = split*4096 + t*128;
    uint32_t bBase = sbase + ((t & 1) ? SM_B1 : SM_B0);
    const float* sq = (const float*)(smem + ((t & 1) ? SM_SQ1 : SM_SQ0));

    uint4 pf[8]; float sqv = 0.f;
    if (t < 31){
      int j0n = j0 + 128;
      #pragma unroll
      for (int l = 0; l < 8; l++){
        int idx = tid + l*256;
        int r = idx >> 4, c = idx & 15;
        pf[l] = ((const uint4*)(g_xbf + (size_t)(j0n + r)*128))[c];
      }
      if (tid < 128) sqv = g_sq[j0n + tid];
    }

    float acc[16][4];
    #pragma unroll
    for (int a = 0; a < 16; a++)
      #pragma unroll
      for (int b = 0; b < 4; b++) acc[a][b] = 0.f;

    #pragma unroll
    for (int ks = 0; ks < 8; ks++){
      uint32_t A[4];
      ldsm4(A[0], A[1], A[2], A[3], aAddr + ks*32);
      #pragma unroll
      for (int p = 0; p < 8; p++){
        uint32_t b0, b1, b2, b3;
        ldsm4(b0, b1, b2, b3, bBase + bRowOff + (uint32_t)(p*16)*PITCH + ks*32);
        mma16816(acc[2*p],   A, b0, b1);
        mma16816(acc[2*p+1], A, b2, b3);
      }
    }

    #pragma unroll
    for (int tt = 0; tt < 16; tt++){
      int c0 = tt*8 + 2*q;
      float sq0 = sq[c0], sq1 = sq[c0 + 1];
      float du0 = fmaf(-2.0f, acc[tt][0], sq0);
      float du1 = fmaf(-2.0f, acc[tt][1], sq1);
      float dl0 = fmaf(-2.0f, acc[tt][2], sq0);
      float dl1 = fmaf(-2.0f, acc[tt][3], sq1);
      if (du0 < thrU){
        ins4(((unsigned long long)encf(du0) << 32) | (unsigned)(j0 + c0), bu);
        thrU = fminf(decf((unsigned)(bu[3] >> 32)), 1e30f);
      }
      if (du1 < thrU){
        ins4(((unsigned long long)encf(du1) << 32) | (unsigned)(j0 + c0 + 1), bu);
        thrU = fminf(decf((unsigned)(bu[3] >> 32)), 1e30f);
      }
      if (dl0 < thrL){
        ins4(((unsigned long long)encf(dl0) << 32) | (unsigned)(j0 + c0), bl);
        thrL = fminf(decf((unsigned)(bl[3] >> 32)), 1e30f);
      }
      if (dl1 < thrL){
        ins4(((unsigned long long)encf(dl1) << 32) | (unsigned)(j0 + c0 + 1), bl);
        thrL = fminf(decf((unsigned)(bl[3] >> 32)), 1e30f);
      }
    }

    if (t < 31){
      char* nb = smem + (((t + 1) & 1) ? SM_B1 : SM_B0);
      #pragma unroll
      for (int l = 0; l < 8; l++){
        int idx = tid + l*256;
        int r = idx >> 4, c = idx & 15;
        *(uint4*)(nb + r*PITCH + c*16) = pf[l];
      }
      if (tid < 128) ((float*)(smem + (((t + 1) & 1) ? SM_SQ1 : SM_SQ0)))[tid] = sqv;
    }
    __syncthreads();
  }

  int rowU = i0 + 16*w + rsub;
  int rowL = rowU + 8;
  size_t baseU = ((size_t)split*NN + rowU)*16 + q*4;
  size_t baseL = ((size_t)split*NN + rowL)*16 + q*4;
  #pragma unroll
  for (int s = 0; s < 4; s++){
    g_cand[baseU + s] = bu[s];
    g_cand[baseL + s] = bl[s];
  }
}

// ---------------- k_rescore: exact fp32, warp per row, coalesced ----------------
__global__ __launch_bounds__(256) void k_rescore(const float* __restrict__ X){
  int g = blockIdx.x*blockDim.x + threadIdx.x;
  int row = g >> 5, lane = g & 31;
  if (row >= NN) return;
  const float4* __restrict__ X4 = (const float4*)X;
  float4 xi = X4[(size_t)row*32 + lane];
  unsigned long long ck = g_cand[((size_t)(lane >> 4)*NN + row)*16 + (lane & 15)];
  int jl = (int)(ck & 0xffffffffull) & (NN - 1);
  float sqi = g_sq[row];
  unsigned long long b0 = ~0ull, b1 = ~0ull, b2 = ~0ull;
  #pragma unroll 4
  for (int c = 0; c < 32; c++){
    int j = __shfl_sync(0xffffffffu, jl, c);
    float4 xj = X4[(size_t)j*32 + lane];
    float p = xi.x*xj.x + xi.y*xj.y + xi.z*xj.z + xi.w*xj.w;
    #pragma unroll
    for (int o = 16; o; o >>= 1) p += __shfl_xor_sync(0xffffffffu, p, o);
    float d2 = (sqi + g_sq[j]) - 2.0f*p;
    unsigned long long key = ((unsigned long long)encf(d2) << 32) | (unsigned)j;
    ins3(key, b0, b1, b2);
  }
  if (lane == 0){
    g_nbr[row*3+0] = (int)(b0 & 0xffffffffull);
    g_nbr[row*3+1] = (int)(b1 & 0xffffffffull);
    g_nbr[row*3+2] = (int)(b2 & 0xffffffffull);
  }
}

// ---------------- k_edge: fused softmax-weight + aggregate (warp per edge-head) ----
__global__ void k_edge(){
  int g = blockIdx.x*blockDim.x + threadIdx.x;
  int eh = g >> 5, lane = g & 31;
  if (eh >= NE*2) return;
  int e = eh >> 1, h = eh & 1;
  int s = e/3;
  int d = g_nbr[e];
  float v = g_as[s*2+h] + g_ad[d*2+h];
  v = v > 0.f ? v : 0.2f*v;
  float w = __expf(v);
  if (lane == 0) atomicAdd(&g_denom[d*2+h], w);
  const float4* xp4 = (const float4*)g_xp;
  float4 xv = xp4[(size_t)s*64 + h*32 + lane];
  float* dst = &g_acc[(size_t)d*256 + h*128 + lane*4];
  atomicAdd(dst+0, w*xv.x);
  atomicAdd(dst+1, w*xv.y);
  atomicAdd(dst+2, w*xv.z);
  atomicAdd(dst+3, w*xv.w);
}

// ---------------- k_final: normalize + head-mean + bias + LN + ReLU + residual -----
__global__ void k_final(const float* __restrict__ X,
                        const float* __restrict__ bias,
                        const float* __restrict__ gamma,
                        const float* __restrict__ beta,
                        float* __restrict__ out){
  int g = blockIdx.x*blockDim.x + threadIdx.x;
  int n = g >> 5, lane = g & 31;
  if (n >= NN) return;
  float inv0 = 1.0f / g_denom[n*2+0];
  float inv1 = 1.0f / g_denom[n*2+1];
  float v[4];
  #pragma unroll
  for (int c = 0; c < 4; c++){
    int dd = lane*4 + c;
    float a0 = g_acc[(size_t)n*256 + dd] * inv0;
    float a1 = g_acc[(size_t)n*256 + 128 + dd] * inv1;
    v[c] = 0.5f*(a0 + a1) + bias[dd];
  }
  float s = v[0]+v[1]+v[2]+v[3];
  #pragma unroll
  for (int o = 16; o; o >>= 1) s += __shfl_xor_sync(0xffffffffu, s, o);
  float mu = s * (1.0f/128.0f);
  float q = 0.f;
  #pragma unroll
  for (int c = 0; c < 4; c++){ float t = v[c]-mu; q += t*t; }
  #pragma unroll
  for (int o = 16; o; o >>= 1) q += __shfl_xor_sync(0xffffffffu, q, o);
  float rstd = rsqrtf(q*(1.0f/128.0f) + 1e-5f);
  #pragma unroll
  for (int c = 0; c < 4; c++){
    int dd = lane*4 + c;
    float y = (v[c]-mu)*rstd*gamma[dd] + beta[dd];
    y = y > 0.f ? y : 0.f;
    out[(size_t)n*128 + dd] = X[(size_t)n*128 + dd] + y;
  }
}

// ---------------- launch ----------------
extern "C" void kernel_launch(void* const* d_in, const int* in_sizes, int n_in,
                              void* d_out, int out_size) {
  const float* prototypes = (const float*)d_in[0];
  // d_in[1] = labels (unused in forward)
  const float* W       = (const float*)d_in[2];
  const float* att_src = (const float*)d_in[3];
  const float* att_dst = (const float*)d_in[4];
  const float* bias    = (const float*)d_in[5];
  const float* gamma   = (const float*)d_in[6];
  const float* beta    = (const float*)d_in[7];
  float* out = (float*)d_out;

  cudaFuncSetAttribute(k_filter, cudaFuncAttributeMaxDynamicSharedMemorySize, SM_TOT);
  cudaFuncSetAttribute(k_xp, cudaFuncAttributeMaxDynamicSharedMemorySize, XP_SMEM);

  // order: k_filter at launch index 3 (the ncu-profiled slot)
  k_prep<<<NN/8, 256>>>((const float4*)prototypes);
  k_xp<<<256, 256, XP_SMEM>>>(prototypes, W);
  k_attn<<<NN/8, 256>>>(att_src, att_dst);
  k_filter<<<128, 256, SM_TOT>>>();
  k_rescore<<<NN/8, 256>>>(prototypes);
  k_edge<<<(NE*2*32+255)/256, 256>>>();
  k_final<<<NN/8, 256>>>(prototypes, bias, gamma, beta, out);
}

// round 11
// speedup vs baseline: 1.2110x; 1.0953x over previous
#include <cuda_runtime.h>
#include <cuda_bf16.h>
#include <cstdint>
#include <math.h>

#define NN 8192
#define DD 128
#define NE (NN*3)

// ---------------- device scratch (no allocations allowed) ----------------
__device__ float g_sq[NN];
__device__ __nv_bfloat16 g_xbf[(size_t)NN*DD];
__device__ unsigned long long g_cand[2ull*NN*32];   // [split][row][32] approx top keys
__device__ int g_nbr[NE];
__device__ float g_xp[(size_t)NN*256];    // x @ W, [N][H=2][128]
__device__ float g_as[NN*2];
__device__ float g_ad[NN*2];
__device__ float g_denom[NN*2];
__device__ float g_acc[(size_t)NN*256];   // unnormalized messages [N][H][128]

__device__ __forceinline__ unsigned encf(float f){
  unsigned u = __float_as_uint(f);
  return (u & 0x80000000u) ? ~u : (u | 0x80000000u);
}
__device__ __forceinline__ float decf(unsigned u){
  return (u & 0x80000000u) ? __uint_as_float(u ^ 0x80000000u) : __uint_as_float(~u);
}
__device__ __forceinline__ void ins3(unsigned long long k,
                                     unsigned long long &b0,
                                     unsigned long long &b1,
                                     unsigned long long &b2){
  if (k < b2){
    if (k < b1){
      b2 = b1;
      if (k < b0){ b1 = b0; b0 = k; } else { b1 = k; }
    } else { b2 = k; }
  }
}
// caller pre-guards with key < b[3]
__device__ __forceinline__ void ins4(unsigned long long k, unsigned long long* b){
  b[3] = k;
  #pragma unroll
  for (int s = 3; s > 0; s--){
    if (b[s] < b[s-1]){ unsigned long long t = b[s]; b[s] = b[s-1]; b[s-1] = t; }
  }
}

__device__ __forceinline__ uint32_t smem_u32(const void* p){
  uint32_t a;
  asm("{ .reg .u64 t; cvta.to.shared.u64 t, %1; cvt.u32.u64 %0, t; }" : "=r"(a) : "l"(p));
  return a;
}
__device__ __forceinline__ void ldsm4(uint32_t &r0, uint32_t &r1, uint32_t &r2, uint32_t &r3, uint32_t a){
  asm volatile("ldmatrix.sync.aligned.m8n8.x4.shared.b16 {%0,%1,%2,%3}, [%4];"
    : "=r"(r0), "=r"(r1), "=r"(r2), "=r"(r3) : "r"(a));
}
__device__ __forceinline__ void mma16816(float* d, const uint32_t* a, uint32_t b0, uint32_t b1){
  asm volatile("mma.sync.aligned.m16n8k16.row.col.f32.bf16.bf16.f32 "
    "{%0,%1,%2,%3}, {%4,%5,%6,%7}, {%8,%9}, {%0,%1,%2,%3};"
    : "+f"(d[0]), "+f"(d[1]), "+f"(d[2]), "+f"(d[3])
    : "r"(a[0]), "r"(a[1]), "r"(a[2]), "r"(a[3]), "r"(b0), "r"(b1));
}

// ---------------- k_prep: fused row squared norm + bf16 convert (warp per row) ----
__global__ void k_prep(const float4* __restrict__ X4){
  int g = blockIdx.x*blockDim.x + threadIdx.x;
  int row = g >> 5, lane = g & 31;
  if (row >= NN) return;
  float4 v = X4[row*32 + lane];
  __nv_bfloat162 p0, p1;
  p0.x = __float2bfloat16(v.x); p0.y = __float2bfloat16(v.y);
  p1.x = __float2bfloat16(v.z); p1.y = __float2bfloat16(v.w);
  ((__nv_bfloat162*)g_xbf)[(size_t)row*64 + lane*2]     = p0;
  ((__nv_bfloat162*)g_xbf)[(size_t)row*64 + lane*2 + 1] = p1;
  float s = v.x*v.x + v.y*v.y + v.z*v.z + v.w*v.w;
  #pragma unroll
  for (int o = 16; o; o >>= 1) s += __shfl_xor_sync(0xffffffffu, s, o);
  if (lane == 0) g_sq[row] = s;
}

// ---------------- k_xp v2: full-K smem, float4 LDS (grid 256 = 128 ib x 2 heads) ---
static constexpr int XP_SMEM = (128*64 + 128*128) * 4;
__global__ __launch_bounds__(256) void k_xp(const float* __restrict__ X,
                                            const float* __restrict__ W){
  extern __shared__ float xsm[];
  float* sA = xsm;
  float* sW = xsm + 128*64;
  const float4* X4 = (const float4*)X;
  const float4* W4 = (const float4*)W;
  int tid = threadIdx.x;
  int tx = tid & 15, ty = tid >> 4;
  int ib = blockIdx.x >> 1, h = blockIdx.x & 1;
  int i0 = ib*64;

  #pragma unroll
  for (int l = 0; l < 8; l++){
    int idx = tid + l*256;
    int r = idx & 63, kc = idx >> 6;
    float4 v = X4[(size_t)(i0 + r)*32 + kc];
    sA[(kc*4+0)*64 + r] = v.x;
    sA[(kc*4+1)*64 + r] = v.y;
    sA[(kc*4+2)*64 + r] = v.z;
    sA[(kc*4+3)*64 + r] = v.w;
  }
  #pragma unroll
  for (int l = 0; l < 16; l++){
    int idx = tid + l*256;
    int k = idx >> 5, c4 = idx & 31;
    ((float4*)sW)[k*32 + c4] = W4[(size_t)k*64 + h*32 + c4];
  }
  __syncthreads();

  float acc[4][8];
  #pragma unroll
  for (int a = 0; a < 4; a++)
    #pragma unroll
    for (int b = 0; b < 8; b++) acc[a][b] = 0.f;

  #pragma unroll 4
  for (int k = 0; k < 128; k++){
    float4 a4 = *(const float4*)(sA + k*64 + 4*ty);
    float4 b0 = *(const float4*)(sW + k*128 + 4*tx);
    float4 b1 = *(const float4*)(sW + k*128 + 64 + 4*tx);
    float a[4] = {a4.x, a4.y, a4.z, a4.w};
    float b[8] = {b0.x, b0.y, b0.z, b0.w, b1.x, b1.y, b1.z, b1.w};
    #pragma unroll
    for (int mi = 0; mi < 4; mi++)
      #pragma unroll
      for (int mj = 0; mj < 8; mj++)
        acc[mi][mj] = fmaf(a[mi], b[mj], acc[mi][mj]);
  }

  #pragma unroll
  for (int mi = 0; mi < 4; mi++){
    size_t base = (size_t)(i0 + 4*ty + mi)*256 + h*128;
    *(float4*)(g_xp + base + 4*tx)      = make_float4(acc[mi][0], acc[mi][1], acc[mi][2], acc[mi][3]);
    *(float4*)(g_xp + base + 64 + 4*tx) = make_float4(acc[mi][4], acc[mi][5], acc[mi][6], acc[mi][7]);
  }
}

// ---------------- k_attn: attention coeffs + init denom/acc ----------------
__global__ void k_attn(const float* __restrict__ att_src,
                       const float* __restrict__ att_dst){
  int g = blockIdx.x*blockDim.x + threadIdx.x;
  int n = g >> 5, lane = g & 31;
  if (n >= NN) return;
  const float4* xp4 = (const float4*)g_xp;
  float4 x0 = xp4[(size_t)n*64 + lane];
  float4 x1 = xp4[(size_t)n*64 + 32 + lane];
  const float4* s4 = (const float4*)att_src;
  const float4* d4 = (const float4*)att_dst;
  float4 a0 = s4[lane], a1 = s4[32 + lane];
  float4 c0 = d4[lane], c1 = d4[32 + lane];
  float vs0 = x0.x*a0.x + x0.y*a0.y + x0.z*a0.z + x0.w*a0.w;
  float vs1 = x1.x*a1.x + x1.y*a1.y + x1.z*a1.z + x1.w*a1.w;
  float vd0 = x0.x*c0.x + x0.y*c0.y + x0.z*c0.z + x0.w*c0.w;
  float vd1 = x1.x*c1.x + x1.y*c1.y + x1.z*c1.z + x1.w*c1.w;
  #pragma unroll
  for (int o = 16; o; o >>= 1){
    vs0 += __shfl_xor_sync(0xffffffffu, vs0, o);
    vs1 += __shfl_xor_sync(0xffffffffu, vs1, o);
    vd0 += __shfl_xor_sync(0xffffffffu, vd0, o);
    vd1 += __shfl_xor_sync(0xffffffffu, vd1, o);
  }
  if (lane == 0){
    g_as[n*2+0] = vs0; g_as[n*2+1] = vs1;
    g_ad[n*2+0] = vd0; g_ad[n*2+1] = vd1;
    g_denom[n*2+0] = 0.f; g_denom[n*2+1] = 0.f;
  }
  float4 z = make_float4(0.f, 0.f, 0.f, 0.f);
  ((float4*)g_acc)[(size_t)n*64 + lane] = z;
  ((float4*)g_acc)[(size_t)n*64 + 32 + lane] = z;
}

// ---------------- k_filter v2: 512 thr, 16 warps; warp = 16 rows x 64 cols --------
// wr = wid&7 (row group), wc = wid>>3 (column half). occ 25%, regs ~100.
static constexpr int PITCH  = 272;
static constexpr int SM_A   = 0;
static constexpr int SM_B0  = 34816;
static constexpr int SM_B1  = 69632;
static constexpr int SM_SQ0 = 104448;
static constexpr int SM_SQ1 = 104960;
static constexpr int SM_TOT = 105472;

__global__ __launch_bounds__(512, 1) void k_filter(){
  extern __shared__ char smem[];
  uint32_t sbase = smem_u32(smem);
  int tid = threadIdx.x;
  int wid = tid >> 5, lane = tid & 31;
  int wr = wid & 7, wc = wid >> 3;
  int ib = blockIdx.x >> 1, split = blockIdx.x & 1;
  int i0 = ib*128;

  // load A tile: 2048 chunks / 512 thr
  #pragma unroll
  for (int l = 0; l < 4; l++){
    int idx = tid + l*512;
    int r = idx >> 4, c = idx & 15;
    uint4 v = ((const uint4*)(g_xbf + (size_t)(i0 + r)*128))[c];
    *(uint4*)(smem + SM_A + r*PITCH + c*16) = v;
  }
  {
    int j0 = split*4096;
    #pragma unroll
    for (int l = 0; l < 4; l++){
      int idx = tid + l*512;
      int r = idx >> 4, c = idx & 15;
      uint4 v = ((const uint4*)(g_xbf + (size_t)(j0 + r)*128))[c];
      *(uint4*)(smem + SM_B0 + r*PITCH + c*16) = v;
    }
    if (tid < 128) ((float*)(smem + SM_SQ0))[tid] = g_sq[j0 + tid];
  }
  __syncthreads();

  uint32_t aAddr = sbase + SM_A
                 + (uint32_t)(16*wr + (lane & 7) + 8*((lane >> 3) & 1))*PITCH
                 + (uint32_t)(((lane >> 4) & 1) << 4);
  uint32_t bRowOff = (uint32_t)(64*wc + (lane & 7) + 8*((lane >> 4) & 1))*PITCH
                   + (uint32_t)(((lane >> 3) & 1) << 4);

  unsigned long long bu[4], bl[4];
  #pragma unroll
  for (int s = 0; s < 4; s++){ bu[s] = ~0ull; bl[s] = ~0ull; }
  float thrU = 1e30f, thrL = 1e30f;

  int q = lane & 3;
  int rsub = lane >> 2;

  for (int t = 0; t < 32; t++){
    int j0 = split*4096 + t*128;
    uint32_t bBase = sbase + ((t & 1) ? SM_B1 : SM_B0);
    const float* sq = (const float*)(smem + ((t & 1) ? SM_SQ1 : SM_SQ0));

    uint4 pf[4]; float sqv = 0.f;
    if (t < 31){
      int j0n = j0 + 128;
      #pragma unroll
      for (int l = 0; l < 4; l++){
        int idx = tid + l*512;
        int r = idx >> 4, c = idx & 15;
        pf[l] = ((const uint4*)(g_xbf + (size_t)(j0n + r)*128))[c];
      }
      if (tid < 128) sqv = g_sq[j0n + tid];
    }

    float acc[8][4];
    #pragma unroll
    for (int a = 0; a < 8; a++)
      #pragma unroll
      for (int b = 0; b < 4; b++) acc[a][b] = 0.f;

    #pragma unroll
    for (int ks = 0; ks < 8; ks++){
      uint32_t A[4];
      ldsm4(A[0], A[1], A[2], A[3], aAddr + ks*32);
      #pragma unroll
      for (int p = 0; p < 4; p++){
        uint32_t b0, b1, b2, b3;
        ldsm4(b0, b1, b2, b3, bBase + bRowOff + (uint32_t)(p*16)*PITCH + ks*32);
        mma16816(acc[2*p],   A, b0, b1);
        mma16816(acc[2*p+1], A, b2, b3);
      }
    }

    // epilogue: d2 = sq_j - 2*dot; float-threshold fast path (NaN-safe update)
    #pragma unroll
    for (int tt = 0; tt < 8; tt++){
      int c0 = 64*wc + 16*(tt >> 1) + 8*(tt & 1) + 2*q;
      float sq0 = sq[c0], sq1 = sq[c0 + 1];
      float du0 = fmaf(-2.0f, acc[tt][0], sq0);
      float du1 = fmaf(-2.0f, acc[tt][1], sq1);
      float dl0 = fmaf(-2.0f, acc[tt][2], sq0);
      float dl1 = fmaf(-2.0f, acc[tt][3], sq1);
      if (du0 < thrU){
        ins4(((unsigned long long)encf(du0) << 32) | (unsigned)(j0 + c0), bu);
        thrU = fminf(decf((unsigned)(bu[3] >> 32)), 1e30f);
      }
      if (du1 < thrU){
        ins4(((unsigned long long)encf(du1) << 32) | (unsigned)(j0 + c0 + 1), bu);
        thrU = fminf(decf((unsigned)(bu[3] >> 32)), 1e30f);
      }
      if (dl0 < thrL){
        ins4(((unsigned long long)encf(dl0) << 32) | (unsigned)(j0 + c0), bl);
        thrL = fminf(decf((unsigned)(bl[3] >> 32)), 1e30f);
      }
      if (dl1 < thrL){
        ins4(((unsigned long long)encf(dl1) << 32) | (unsigned)(j0 + c0 + 1), bl);
        thrL = fminf(decf((unsigned)(bl[3] >> 32)), 1e30f);
      }
    }

    if (t < 31){
      char* nb = smem + (((t + 1) & 1) ? SM_B1 : SM_B0);
      #pragma unroll
      for (int l = 0; l < 4; l++){
        int idx = tid + l*512;
        int r = idx >> 4, c = idx & 15;
        *(uint4*)(nb + r*PITCH + c*16) = pf[l];
      }
      if (tid < 128) ((float*)(smem + (((t + 1) & 1) ? SM_SQ1 : SM_SQ0)))[tid] = sqv;
    }
    __syncthreads();
  }

  // write per-(row, wc, q) top-4: rows 16wr + rsub and +8
  int rowU = i0 + 16*wr + rsub;
  int rowL = rowU + 8;
  size_t baseU = ((size_t)split*NN + rowU)*32 + wc*16 + q*4;
  size_t baseL = ((size_t)split*NN + rowL)*32 + wc*16 + q*4;
  #pragma unroll
  for (int s = 0; s < 4; s++){
    g_cand[baseU + s] = bu[s];
    g_cand[baseL + s] = bl[s];
  }
}

// ---------------- k_rescore: exact fp32, warp per row, 64 candidates --------------
__global__ __launch_bounds__(256) void k_rescore(const float* __restrict__ X){
  int g = blockIdx.x*blockDim.x + threadIdx.x;
  int row = g >> 5, lane = g & 31;
  if (row >= NN) return;
  const float4* __restrict__ X4 = (const float4*)X;
  float4 xi = X4[(size_t)row*32 + lane];
  unsigned long long k0 = g_cand[(size_t)row*32 + lane];            // split 0
  unsigned long long k1 = g_cand[((size_t)NN + row)*32 + lane];     // split 1
  int jl0 = (int)(k0 & 0xffffffffull) & (NN - 1);
  int jl1 = (int)(k1 & 0xffffffffull) & (NN - 1);
  float sqi = g_sq[row];
  unsigned long long b0 = ~0ull, b1 = ~0ull, b2 = ~0ull;
  #pragma unroll 4
  for (int c = 0; c < 32; c++){
    int ja = __shfl_sync(0xffffffffu, jl0, c);
    int jb = __shfl_sync(0xffffffffu, jl1, c);
    float4 xa = X4[(size_t)ja*32 + lane];
    float4 xb = X4[(size_t)jb*32 + lane];
    float pa = xi.x*xa.x + xi.y*xa.y + xi.z*xa.z + xi.w*xa.w;
    float pb = xi.x*xb.x + xi.y*xb.y + xi.z*xb.z + xi.w*xb.w;
    #pragma unroll
    for (int o = 16; o; o >>= 1){
      pa += __shfl_xor_sync(0xffffffffu, pa, o);
      pb += __shfl_xor_sync(0xffffffffu, pb, o);
    }
    float d2a = (sqi + g_sq[ja]) - 2.0f*pa;
    float d2b = (sqi + g_sq[jb]) - 2.0f*pb;
    ins3(((unsigned long long)encf(d2a) << 32) | (unsigned)ja, b0, b1, b2);
    ins3(((unsigned long long)encf(d2b) << 32) | (unsigned)jb, b0, b1, b2);
  }
  if (lane == 0){
    g_nbr[row*3+0] = (int)(b0 & 0xffffffffull);
    g_nbr[row*3+1] = (int)(b1 & 0xffffffffull);
    g_nbr[row*3+2] = (int)(b2 & 0xffffffffull);
  }
}

// ---------------- k_edge: fused softmax-weight + aggregate (warp per edge-head) ----
__global__ void k_edge(){
  int g = blockIdx.x*blockDim.x + threadIdx.x;
  int eh = g >> 5, lane = g & 31;
  if (eh >= NE*2) return;
  int e = eh >> 1, h = eh & 1;
  int s = e/3;
  int d = g_nbr[e];
  float v = g_as[s*2+h] + g_ad[d*2+h];
  v = v > 0.f ? v : 0.2f*v;
  float w = __expf(v);
  if (lane == 0) atomicAdd(&g_denom[d*2+h], w);
  const float4* xp4 = (const float4*)g_xp;
  float4 xv = xp4[(size_t)s*64 + h*32 + lane];
  float* dst = &g_acc[(size_t)d*256 + h*128 + lane*4];
  atomicAdd(dst+0, w*xv.x);
  atomicAdd(dst+1, w*xv.y);
  atomicAdd(dst+2, w*xv.z);
  atomicAdd(dst+3, w*xv.w);
}

// ---------------- k_final: normalize + head-mean + bias + LN + ReLU + residual -----
__global__ void k_final(const float* __restrict__ X,
                        const float* __restrict__ bias,
                        const float* __restrict__ gamma,
                        const float* __restrict__ beta,
                        float* __restrict__ out){
  int g = blockIdx.x*blockDim.x + threadIdx.x;
  int n = g >> 5, lane = g & 31;
  if (n >= NN) return;
  float inv0 = 1.0f / g_denom[n*2+0];
  float inv1 = 1.0f / g_denom[n*2+1];
  float v[4];
  #pragma unroll
  for (int c = 0; c < 4; c++){
    int dd = lane*4 + c;
    float a0 = g_acc[(size_t)n*256 + dd] * inv0;
    float a1 = g_acc[(size_t)n*256 + 128 + dd] * inv1;
    v[c] = 0.5f*(a0 + a1) + bias[dd];
  }
  float s = v[0]+v[1]+v[2]+v[3];
  #pragma unroll
  for (int o = 16; o; o >>= 1) s += __shfl_xor_sync(0xffffffffu, s, o);
  float mu = s * (1.0f/128.0f);
  float q = 0.f;
  #pragma unroll
  for (int c = 0; c < 4; c++){ float t = v[c]-mu; q += t*t; }
  #pragma unroll
  for (int o = 16; o; o >>= 1) q += __shfl_xor_sync(0xffffffffu, q, o);
  float rstd = rsqrtf(q*(1.0f/128.0f) + 1e-5f);
  #pragma unroll
  for (int c = 0; c < 4; c++){
    int dd = lane*4 + c;
    float y = (v[c]-mu)*rstd*gamma[dd] + beta[dd];
    y = y > 0.f ? y : 0.f;
    out[(size_t)n*128 + dd] = X[(size_t)n*128 + dd] + y;
  }
}

// ---------------- launch ----------------
extern "C" void kernel_launch(void* const* d_in, const int* in_sizes, int n_in,
                              void* d_out, int out_size) {
  const float* prototypes = (const float*)d_in[0];
  // d_in[1] = labels (unused in forward)
  const float* W       = (const float*)d_in[2];
  const float* att_src = (const float*)d_in[3];
  const float* att_dst = (const float*)d_in[4];
  const float* bias    = (const float*)d_in[5];
  const float* gamma   = (const float*)d_in[6];
  const float* beta    = (const float*)d_in[7];
  float* out = (float*)d_out;

  cudaFuncSetAttribute(k_filter, cudaFuncAttributeMaxDynamicSharedMemorySize, SM_TOT);
  cudaFuncSetAttribute(k_xp, cudaFuncAttributeMaxDynamicSharedMemorySize, XP_SMEM);

  // order: k_filter at launch index 3 (the ncu-profiled slot)
  k_prep<<<NN/8, 256>>>((const float4*)prototypes);
  k_xp<<<256, 256, XP_SMEM>>>(prototypes, W);
  k_attn<<<NN/8, 256>>>(att_src, att_dst);
  k_filter<<<128, 512, SM_TOT>>>();
  k_rescore<<<NN/8, 256>>>(prototypes);
  k_edge<<<(NE*2*32+255)/256, 256>>>();
  k_final<<<NN/8, 256>>>(prototypes, bias, gamma, beta, out);
}